// round 15
// baseline (speedup 1.0000x reference)
#include <cuda_runtime.h>
#include <cuda_fp16.h>
#include <cstdint>

#define N_TOKENS 8192
#define D_MODEL  1024
#define D_FF     4096
#define TOPK     2
#define N_EXPERTS 8
#define CAP      4096
#define TOTAL    (N_TOKENS*TOPK)

#define G1_BLOCKS (64*32*N_EXPERTS)     // 16384
#define G2_BLOCKS (8*32*N_EXPERTS)      // 2048

// prep kernel: blocks [0,64) route, [64, 64+49152) transposes
#define PREP_ROUTE 64
#define PREP_BLOCKS (PREP_ROUTE + 49152)

// ---------------- device scratch ----------------
__device__ int    g_cnt_raw[N_EXPERTS];
__device__ int    g_done[N_EXPERTS*32];     // GEMM1 nt-completions per (e,mt)
__device__ int    g_rowtok[N_EXPERTS*CAP];
__device__ int    g_slotof[TOTAL];
__device__ __half g_xr [(size_t)N_TOKENS*D_MODEL];
__device__ __half g_w1t[(size_t)N_EXPERTS*D_FF*D_MODEL];
__device__ __half g_w2t[(size_t)N_EXPERTS*D_FF*D_MODEL];
__device__ __half g_w3t[(size_t)N_EXPERTS*D_MODEL*D_FF];
__device__ __half g_G  [(size_t)N_EXPERTS*CAP*D_FF];
__device__ float  g_Y  [(size_t)N_EXPERTS*CAP*D_MODEL];

// ---------------- helpers ----------------
__device__ __forceinline__ uint32_t smem_u32(const void* p){
    uint32_t a;
    asm("{ .reg .u64 t; cvta.to.shared.u64 t, %1; cvt.u32.u64 %0, t; }" : "=r"(a) : "l"(p));
    return a;
}
__device__ __forceinline__ void cp16(uint32_t s, const void* g, uint32_t n){
    asm volatile("cp.async.cg.shared.global [%0], [%1], 16, %2;" :: "r"(s), "l"(g), "r"(n));
}
#define CP_COMMIT() asm volatile("cp.async.commit_group;" ::: "memory")
#define CP_WAIT(n)  asm volatile("cp.async.wait_group %0;" :: "n"(n) : "memory")
#define BAR_SYNC(id) asm volatile("bar.sync %0, 64;" :: "r"(id) : "memory")

__device__ __forceinline__ void ldsm4(uint32_t& r0, uint32_t& r1, uint32_t& r2, uint32_t& r3, uint32_t a){
    asm volatile("ldmatrix.sync.aligned.m8n8.x4.shared.b16 {%0,%1,%2,%3}, [%4];"
        : "=r"(r0), "=r"(r1), "=r"(r2), "=r"(r3) : "r"(a));
}
__device__ __forceinline__ void mma_f16(float& c0, float& c1, float& c2, float& c3,
                                        uint32_t a0, uint32_t a1, uint32_t a2, uint32_t a3,
                                        uint32_t b0, uint32_t b1){
    asm volatile("mma.sync.aligned.m16n8k16.row.col.f32.f16.f16.f32 "
        "{%0,%1,%2,%3}, {%4,%5,%6,%7}, {%8,%9}, {%0,%1,%2,%3};"
        : "+f"(c0), "+f"(c1), "+f"(c2), "+f"(c3)
        : "r"(a0), "r"(a1), "r"(a2), "r"(a3), "r"(b0), "r"(b1));
}

#define STAGE_B   32768
#define B_OFF     16384
#define SMEM_BYTES 98304
#define EP_PITCH  136

// ---------------- init (launch 0) ----------------
__global__ void init_kernel(){
    int t = threadIdx.x;
    if (t < N_EXPERTS) g_cnt_raw[t] = 0;
    if (t < N_EXPERTS*32) g_done[t] = 0;
}
// ---------------- x -> fp16 (launch 1) ----------------
__global__ void round_x_kernel(const float* __restrict__ x){
    int i = blockIdx.x * blockDim.x + threadIdx.x;
    if (i >= N_TOKENS*D_MODEL/4) return;
    float4 v = ((const float4*)x)[i];
    ((__half2*)g_xr)[2*i]   = __halves2half2(__float2half_rn(v.x), __float2half_rn(v.y));
    ((__half2*)g_xr)[2*i+1] = __halves2half2(__float2half_rn(v.z), __float2half_rn(v.w));
}
// ---------------- prep: route (64 blocks) + all transposes (launch 2) ----------------
__global__ void prep_kernel(const int* __restrict__ eidx,
                            const float* __restrict__ w1,
                            const float* __restrict__ w2,
                            const float* __restrict__ w3){
    if (blockIdx.x < PREP_ROUTE){
        int i = blockIdx.x * 256 + threadIdx.x;
        if (i < TOTAL){
            int e = eidx[i] & (N_EXPERTS - 1);
            int pos = atomicAdd(&g_cnt_raw[e], 1);
            if (pos < CAP){ g_rowtok[e*CAP + pos] = i >> 1; g_slotof[i] = e*CAP + pos; }
            else g_slotof[i] = -1;
        }
        return;
    }
    __shared__ float tile[64][33];
    int i = blockIdx.x - PREP_ROUTE;
    int m = i >> 14, r = i & 16383, e = r >> 11, tt = r & 2047;
    const float* src; __half* dst; int R, C, by, bx;
    if (m == 0){ src = w1; dst = g_w1t; R = D_MODEL; C = D_FF; by = tt>>7; bx = tt&127; }
    else if (m == 1){ src = w2; dst = g_w2t; R = D_MODEL; C = D_FF; by = tt>>7; bx = tt&127; }
    else { src = w3; dst = g_w3t; R = D_FF; C = D_MODEL; by = tt>>5; bx = tt&31; }
    const float* s = src + (size_t)e*R*C;
    __half* d = dst + (size_t)e*R*C;
    int r0 = by*64, c0 = bx*32;
    int tx = threadIdx.x & 31, ty = threadIdx.x >> 5;
    #pragma unroll
    for (int k = 0; k < 64; k += 8)
        tile[ty + k][tx] = s[(size_t)(r0 + ty + k) * C + c0 + tx];
    __syncthreads();
    #pragma unroll
    for (int it = 0; it < 4; it++){
        int j = ty*4 + it;
        __half2 v = __halves2half2(__float2half_rn(tile[2*tx][j]),
                                   __float2half_rn(tile[2*tx+1][j]));
        ((__half2*)(d + (size_t)(c0 + j)*R + r0))[tx] = v;
    }
}

// ---------------- GEMM body (128x128 CTA, 4 warps 2x2 of 64x64, 3-stage) ----------------
// Per-warp fill ownership: warp (wm,wn) fills A rows [wm*64+wn*32,+32), B rows [wn*64+wm*32,+32).
// Chunk-top sync = two 64-thread named barriers (A-pair, B-pair) instead of __syncthreads.
template<int MODE>
__device__ __forceinline__ void gemm_body(int nt, int mt, int e, int cnt, char* smem){
    const int NCH = (MODE == 0) ? (D_MODEL/64) : (D_FF/64);
    uint32_t sbase = smem_u32(smem);
    int tid = threadIdx.x;
    int wid = tid >> 5, lid = tid & 31;
    int wm = wid >> 1, wn = wid & 1;
    int g = lid >> 2, t = lid & 3;
    int g8 = lid >> 3, sc = lid & 7;
    int barA = 1 + wm, barB = 3 + wn;

    int arow0 = wm*64 + wn*32 + g8;            // + 4j
    int brow0 = wn*64 + wm*32 + g8;            // + 4j

    const char* abase;
    uint32_t aoff[8];
    uint32_t amask = 0;
    const __half* bb0;
    size_t bstep;
    if (MODE == 0){
        abase = (const char*)g_xr;
        #pragma unroll
        for (int j = 0; j < 8; j++){
            int grow = mt*128 + arow0 + 4*j;
            int tok = (grow < cnt) ? g_rowtok[e*CAP + grow] : -1;
            aoff[j] = (tok >= 0) ? ((uint32_t)tok*(D_MODEL*2) + sc*16) : 0;
            if (tok >= 0) amask |= (1u << j);
        }
        const __half* wb = (brow0 & 1) ? g_w2t : g_w1t;
        bb0 = wb + ((size_t)e*D_FF + nt*64 + (brow0 >> 1))*D_MODEL + sc*8;
        bstep = (size_t)2*D_MODEL;             // rows advance by 4 -> n-index by 2
    } else {
        abase = (const char*)(g_G + ((size_t)(e*CAP + mt*128 + arow0))*D_FF + sc*8);
        #pragma unroll
        for (int j = 0; j < 8; j++){ aoff[j] = (uint32_t)(4*j)*D_FF*2; amask |= (1u<<j); }
        bb0 = g_w3t + ((size_t)e*D_MODEL + nt*128 + brow0)*D_FF + sc*8;
        bstep = (size_t)4*D_FF;
    }
    uint32_t adst[8], bdst[8];
    #pragma unroll
    for (int j = 0; j < 8; j++){
        uint32_t ar = (uint32_t)(arow0 + 4*j), br = (uint32_t)(brow0 + 4*j);
        adst[j] = sbase + ar*128u + (((uint32_t)sc ^ (ar & 7u)) << 4);
        bdst[j] = sbase + B_OFF + br*128u + (((uint32_t)sc ^ (br & 7u)) << 4);
    }
    uint32_t albase[4], blbase[4];
    #pragma unroll
    for (int mf = 0; mf < 4; mf++){
        uint32_t row = (uint32_t)(wm*64 + mf*16 + (lid & 15));
        albase[mf] = sbase + row*128u + ((row & 7u) << 4);
    }
    #pragma unroll
    for (int j = 0; j < 4; j++){
        uint32_t row = (uint32_t)(wn*64 + j*16 + (lid & 7) + ((lid >> 4) & 1)*8);
        blbase[j] = sbase + B_OFF + row*128u + ((row & 7u) << 4);
    }
    uint32_t a_sl_hi = (uint32_t)(lid >> 4);
    uint32_t b_sl_hi = (uint32_t)((lid >> 3) & 1);

    float c[4][8][4];
    #pragma unroll
    for (int mf = 0; mf < 4; mf++)
        #pragma unroll
        for (int nf = 0; nf < 8; nf++)
            #pragma unroll
            for (int i = 0; i < 4; i++) c[mf][nf][i] = 0.f;

    // prologue: chunks 0,1 -> stages 0,1
    #pragma unroll
    for (int pc = 0; pc < 2; pc++){
        uint32_t so = pc*STAGE_B;
        #pragma unroll
        for (int j = 0; j < 8; j++){
            cp16(adst[j] + so, abase + aoff[j] + (size_t)pc*128, ((amask>>j)&1) ? 16u : 0u);
            cp16(bdst[j] + so, bb0 + (size_t)j*bstep + pc*64, 16u);
        }
        CP_COMMIT();
    }

    #pragma unroll 1
    for (int kc = 0; kc < NCH; kc++){
        if (kc == NCH-1) { CP_WAIT(0); } else { CP_WAIT(1); }
        BAR_SYNC(barA);
        BAR_SYNC(barB);
        uint32_t so = (kc%3)*STAGE_B;
        #pragma unroll
        for (int kk = 0; kk < 4; kk++){
            uint32_t a[4][4];
            #pragma unroll
            for (int mf = 0; mf < 4; mf++){
                uint32_t sl = (uint32_t)(2*kk) + a_sl_hi;
                ldsm4(a[mf][0], a[mf][1], a[mf][2], a[mf][3], (albase[mf] ^ (sl<<4)) + so);
            }
            uint32_t b[8][2];
            #pragma unroll
            for (int j = 0; j < 4; j++){
                uint32_t sl = (uint32_t)(2*kk) + b_sl_hi;
                ldsm4(b[2*j][0], b[2*j][1], b[2*j+1][0], b[2*j+1][1], (blbase[j] ^ (sl<<4)) + so);
            }
            #pragma unroll
            for (int mf = 0; mf < 4; mf++)
                #pragma unroll
                for (int nf = 0; nf < 8; nf++)
                    mma_f16(c[mf][nf][0], c[mf][nf][1], c[mf][nf][2], c[mf][nf][3],
                            a[mf][0], a[mf][1], a[mf][2], a[mf][3],
                            b[nf][0], b[nf][1]);
            // prefetch next chunk: A after kk0, B (+commit) after kk1
            if (kk == 0 && kc + 2 < NCH){
                uint32_t po = ((kc+2)%3)*STAGE_B;
                #pragma unroll
                for (int j = 0; j < 8; j++)
                    cp16(adst[j] + po, abase + aoff[j] + (size_t)(kc+2)*128, ((amask>>j)&1) ? 16u : 0u);
            }
            if (kk == 1 && kc + 2 < NCH){
                uint32_t po = ((kc+2)%3)*STAGE_B;
                #pragma unroll
                for (int j = 0; j < 8; j++)
                    cp16(bdst[j] + po, bb0 + (size_t)j*bstep + (size_t)(kc+2)*64, 16u);
                CP_COMMIT();
            }
        }
    }

    if (MODE == 0){
        __syncthreads();
        __half* ep = (__half*)smem;
        #pragma unroll
        for (int mf = 0; mf < 4; mf++){
            #pragma unroll
            for (int i2 = 0; i2 < 2; i2++){
                int mrow = wm*64 + mf*16 + i2*8 + g;
                __half* er = ep + mrow*EP_PITCH + wn*32;
                #pragma unroll
                for (int nf = 0; nf < 8; nf++){
                    float h = c[mf][nf][i2*2 + 0];
                    float v = c[mf][nf][i2*2 + 1];
                    er[nf*4 + t] = __float2half_rn(h * v / (1.f + __expf(-h)));
                }
            }
        }
        __syncthreads();
        int gg = tid >> 3, sl = tid & 7;
        #pragma unroll
        for (int j = 0; j < 8; j++){
            int row = gg*8 + j;
            float4 v = *(const float4*)(ep + row*EP_PITCH + sl*8);
            *(float4*)(g_G + ((size_t)(e*CAP + mt*128 + row))*D_FF + nt*64 + sl*8) = v;
        }
        __threadfence();
        __syncthreads();
        if (tid == 0) atomicAdd(&g_done[e*32 + mt], 1);
    } else {
        #pragma unroll
        for (int mf = 0; mf < 4; mf++){
            #pragma unroll
            for (int i2 = 0; i2 < 2; i2++){
                int m = mt*128 + wm*64 + mf*16 + i2*8 + g;
                float* yd = g_Y + ((size_t)(e*CAP + m))*D_MODEL + nt*128 + wn*64;
                #pragma unroll
                for (int nf = 0; nf < 8; nf++){
                    float2 o = make_float2(c[mf][nf][i2*2 + 0], c[mf][nf][i2*2 + 1]);
                    *(float2*)(yd + nf*8 + 2*t) = o;
                }
            }
        }
    }
}

// ---------------- fused GEMM1+GEMM2 (launch 3) ----------------
__global__ void __launch_bounds__(128, 2) gemm_fused_kernel(){
    extern __shared__ char smem[];
    int bid = blockIdx.x;
    if (bid < G1_BLOCKS){
        int nt = bid & 63, mt = (bid >> 6) & 31, e = bid >> 11;
        int c0 = g_cnt_raw[e]; int cnt = c0 < CAP ? c0 : CAP;
        if (mt*128 >= cnt) return;
        gemm_body<0>(nt, mt, e, cnt, smem);
    } else {
        int b = bid - G1_BLOCKS;
        int nt = b & 7, mt = (b >> 3) & 31, e = b >> 8;
        int c0 = g_cnt_raw[e]; int cnt = c0 < CAP ? c0 : CAP;
        if (mt*128 >= cnt) return;
        if (threadIdx.x == 0){
            while (atomicAdd(&g_done[e*32 + mt], 0) < 64) __nanosleep(200);
        }
        __syncthreads();
        __threadfence();
        gemm_body<1>(nt, mt, e, cnt, smem);
    }
}

// ---------------- weighted top-k combine (launch 4) ----------------
__global__ void combine_kernel(const float* __restrict__ ew, float* __restrict__ out){
    int i = blockIdx.x * blockDim.x + threadIdx.x;
    if (i >= N_TOKENS*D_MODEL/4) return;
    int tok = i >> 8;
    int d4 = i & 255;
    float4 acc = make_float4(0.f,0.f,0.f,0.f);
    #pragma unroll
    for (int k = 0; k < TOPK; k++){
        int s = g_slotof[2*tok + k];
        if (s >= 0){
            float w = ew[2*tok + k];
            float4 v = ((const float4*)g_Y)[(size_t)s*(D_MODEL/4) + d4];
            acc.x += w*v.x; acc.y += w*v.y; acc.z += w*v.z; acc.w += w*v.w;
        }
    }
    ((float4*)out)[i] = acc;
}

extern "C" void kernel_launch(void* const* d_in, const int* in_sizes, int n_in,
                              void* d_out, int out_size) {
    const float* x   = (const float*)d_in[0];
    const int*   idx = (const int*)  d_in[1];
    const float* ew  = (const float*)d_in[2];
    const float* w1  = (const float*)d_in[3];
    const float* w2  = (const float*)d_in[4];
    const float* w3  = (const float*)d_in[5];
    float* out = (float*)d_out;

    cudaFuncSetAttribute(gemm_fused_kernel, cudaFuncAttributeMaxDynamicSharedMemorySize, SMEM_BYTES);

    init_kernel<<<1, 256>>>();                                        // 0
    round_x_kernel<<<(N_TOKENS*D_MODEL/4)/256, 256>>>(x);             // 1
    prep_kernel<<<PREP_BLOCKS, 256>>>(idx, w1, w2, w3);               // 2 (route + transposes)
    gemm_fused_kernel<<<G1_BLOCKS + G2_BLOCKS, 128, SMEM_BYTES>>>();  // 3 <- ncu slot
    combine_kernel<<<(N_TOKENS*D_MODEL/4)/256, 256>>>(ew, out);       // 4
}

// round 16
// speedup vs baseline: 1.0301x; 1.0301x over previous
#include <cuda_runtime.h>
#include <cuda_fp16.h>
#include <cstdint>

#define N_TOKENS 8192
#define D_MODEL  1024
#define D_FF     4096
#define TOPK     2
#define N_EXPERTS 8
#define CAP      4096
#define TOTAL    (N_TOKENS*TOPK)

#define G1_BLOCKS (64*32*N_EXPERTS)     // 16384
#define G2_BLOCKS (8*32*N_EXPERTS)      // 2048

// prep kernel: [0,64) route, [64, 64+8192) x->fp16, [8256, +49152) transposes
#define PREP_ROUTE 64
#define PREP_RX    8192
#define PREP_TBASE (PREP_ROUTE + PREP_RX)
#define PREP_BLOCKS (PREP_TBASE + 49152)

// ---------------- device scratch ----------------
__device__ int    g_cnt_raw[N_EXPERTS];
__device__ int    g_done[N_EXPERTS*32];     // GEMM1 nt-completions per (e,mt)
__device__ int    g_rowtok[N_EXPERTS*CAP];
__device__ int    g_slotof[TOTAL];
__device__ __half g_xr [(size_t)N_TOKENS*D_MODEL];
__device__ __half g_w1t[(size_t)N_EXPERTS*D_FF*D_MODEL];
__device__ __half g_w2t[(size_t)N_EXPERTS*D_FF*D_MODEL];
__device__ __half g_w3t[(size_t)N_EXPERTS*D_MODEL*D_FF];
__device__ __half g_G  [(size_t)N_EXPERTS*CAP*D_FF];
__device__ __half g_Y  [(size_t)N_EXPERTS*CAP*D_MODEL];

// ---------------- helpers ----------------
__device__ __forceinline__ uint32_t smem_u32(const void* p){
    uint32_t a;
    asm("{ .reg .u64 t; cvta.to.shared.u64 t, %1; cvt.u32.u64 %0, t; }" : "=r"(a) : "l"(p));
    return a;
}
__device__ __forceinline__ void cp16(uint32_t s, const void* g, uint32_t n){
    asm volatile("cp.async.cg.shared.global [%0], [%1], 16, %2;" :: "r"(s), "l"(g), "r"(n));
}
#define CP_COMMIT() asm volatile("cp.async.commit_group;" ::: "memory")
#define CP_WAIT(n)  asm volatile("cp.async.wait_group %0;" :: "n"(n) : "memory")

__device__ __forceinline__ void ldsm4(uint32_t& r0, uint32_t& r1, uint32_t& r2, uint32_t& r3, uint32_t a){
    asm volatile("ldmatrix.sync.aligned.m8n8.x4.shared.b16 {%0,%1,%2,%3}, [%4];"
        : "=r"(r0), "=r"(r1), "=r"(r2), "=r"(r3) : "r"(a));
}
__device__ __forceinline__ void mma_f16(float& c0, float& c1, float& c2, float& c3,
                                        uint32_t a0, uint32_t a1, uint32_t a2, uint32_t a3,
                                        uint32_t b0, uint32_t b1){
    asm volatile("mma.sync.aligned.m16n8k16.row.col.f32.f16.f16.f32 "
        "{%0,%1,%2,%3}, {%4,%5,%6,%7}, {%8,%9}, {%0,%1,%2,%3};"
        : "+f"(c0), "+f"(c1), "+f"(c2), "+f"(c3)
        : "r"(a0), "r"(a1), "r"(a2), "r"(a3), "r"(b0), "r"(b1));
}

#define STAGE_B   32768
#define B_OFF     16384
#define SMEM_BYTES 98304
#define EP_PITCH  136

// ---------------- init (launch 0) ----------------
__global__ void init_kernel(){
    int t = threadIdx.x;
    if (t < N_EXPERTS) g_cnt_raw[t] = 0;
    if (t < N_EXPERTS*32) g_done[t] = 0;
}
// ---------------- prep: route + x->fp16 + all transposes (launch 1) ----------------
__global__ void prep_kernel(const int* __restrict__ eidx,
                            const float* __restrict__ x,
                            const float* __restrict__ w1,
                            const float* __restrict__ w2,
                            const float* __restrict__ w3){
    if (blockIdx.x < PREP_ROUTE){
        int i = blockIdx.x * 256 + threadIdx.x;
        if (i < TOTAL){
            int e = eidx[i] & (N_EXPERTS - 1);
            int pos = atomicAdd(&g_cnt_raw[e], 1);
            if (pos < CAP){ g_rowtok[e*CAP + pos] = i >> 1; g_slotof[i] = e*CAP + pos; }
            else g_slotof[i] = -1;
        }
        return;
    }
    if (blockIdx.x < PREP_TBASE){
        int i = (blockIdx.x - PREP_ROUTE) * 256 + threadIdx.x;
        if (i < N_TOKENS*D_MODEL/4){
            float4 v = ((const float4*)x)[i];
            ((__half2*)g_xr)[2*i]   = __halves2half2(__float2half_rn(v.x), __float2half_rn(v.y));
            ((__half2*)g_xr)[2*i+1] = __halves2half2(__float2half_rn(v.z), __float2half_rn(v.w));
        }
        return;
    }
    __shared__ float tile[64][33];
    int i = blockIdx.x - PREP_TBASE;
    int m = i >> 14, r = i & 16383, e = r >> 11, tt = r & 2047;
    const float* src; __half* dst; int R, C, by, bx;
    if (m == 0){ src = w1; dst = g_w1t; R = D_MODEL; C = D_FF; by = tt>>7; bx = tt&127; }
    else if (m == 1){ src = w2; dst = g_w2t; R = D_MODEL; C = D_FF; by = tt>>7; bx = tt&127; }
    else { src = w3; dst = g_w3t; R = D_FF; C = D_MODEL; by = tt>>5; bx = tt&31; }
    const float* s = src + (size_t)e*R*C;
    __half* d = dst + (size_t)e*R*C;
    int r0 = by*64, c0 = bx*32;
    int tx = threadIdx.x & 31, ty = threadIdx.x >> 5;
    #pragma unroll
    for (int k = 0; k < 64; k += 8)
        tile[ty + k][tx] = s[(size_t)(r0 + ty + k) * C + c0 + tx];
    __syncthreads();
    #pragma unroll
    for (int it = 0; it < 4; it++){
        int j = ty*4 + it;
        __half2 v = __halves2half2(__float2half_rn(tile[2*tx][j]),
                                   __float2half_rn(tile[2*tx+1][j]));
        ((__half2*)(d + (size_t)(c0 + j)*R + r0))[tx] = v;
    }
}

// ---------------- GEMM body (128x128 CTA, 4 warps 2x2 of 64x64, 3-stage) ----------------
// R14 structure: kk0 compute first, then next-chunk cp.async prefetch, then kk1..3.
template<int MODE>
__device__ __forceinline__ void gemm_body(int nt, int mt, int e, int cnt, char* smem){
    const int NCH = (MODE == 0) ? (D_MODEL/64) : (D_FF/64);
    uint32_t sbase = smem_u32(smem);
    int tid = threadIdx.x;
    int wid = tid >> 5, lid = tid & 31;
    int wm = wid >> 1, wn = wid & 1;
    int g = lid >> 2, t = lid & 3;
    int r0 = tid >> 3;
    int sc = tid & 7;

    const char* abase;
    uint32_t aoff[8];
    uint32_t amask = 0;
    const __half* bbase;
    size_t bstride;
    if (MODE == 0){
        abase = (const char*)g_xr;
        #pragma unroll
        for (int it = 0; it < 8; it++){
            int grow = mt*128 + r0 + it*16;
            int tok = (grow < cnt) ? g_rowtok[e*CAP + grow] : -1;
            aoff[it] = (tok >= 0) ? ((uint32_t)tok*(D_MODEL*2) + sc*16) : 0;
            if (tok >= 0) amask |= (1u << it);
        }
        const __half* wb = (r0 & 1) ? g_w2t : g_w1t;
        bbase = wb + ((size_t)e*D_FF + nt*64 + (r0 >> 1))*D_MODEL + sc*8;
        bstride = (size_t)8*D_MODEL;
    } else {
        abase = (const char*)(g_G + ((size_t)(e*CAP + mt*128 + r0))*D_FF + sc*8);
        #pragma unroll
        for (int it = 0; it < 8; it++){ aoff[it] = (uint32_t)it*16*D_FF*2; amask |= (1u<<it); }
        bbase = g_w3t + ((size_t)e*D_MODEL + nt*128 + r0)*D_FF + sc*8;
        bstride = (size_t)16*D_FF;
    }
    uint32_t adst[8], bdst[8];
    #pragma unroll
    for (int it = 0; it < 8; it++){
        uint32_t row = (uint32_t)(r0 + it*16);
        uint32_t seg = ((uint32_t)sc ^ (row & 7u)) << 4;
        adst[it] = sbase + row*128u + seg;
        bdst[it] = sbase + B_OFF + row*128u + seg;
    }
    uint32_t albase[4], blbase[4];
    #pragma unroll
    for (int mf = 0; mf < 4; mf++){
        uint32_t row = (uint32_t)(wm*64 + mf*16 + (lid & 15));
        albase[mf] = sbase + row*128u + ((row & 7u) << 4);
    }
    #pragma unroll
    for (int j = 0; j < 4; j++){
        uint32_t row = (uint32_t)(wn*64 + j*16 + (lid & 7) + ((lid >> 4) & 1)*8);
        blbase[j] = sbase + B_OFF + row*128u + ((row & 7u) << 4);
    }
    uint32_t a_sl_hi = (uint32_t)(lid >> 4);
    uint32_t b_sl_hi = (uint32_t)((lid >> 3) & 1);

    float c[4][8][4];
    #pragma unroll
    for (int mf = 0; mf < 4; mf++)
        #pragma unroll
        for (int nf = 0; nf < 8; nf++)
            #pragma unroll
            for (int i = 0; i < 4; i++) c[mf][nf][i] = 0.f;

    #pragma unroll
    for (int pc = 0; pc < 2; pc++){
        uint32_t so = pc*STAGE_B;
        #pragma unroll
        for (int it = 0; it < 8; it++){
            cp16(adst[it] + so, abase + aoff[it] + (size_t)pc*128, ((amask>>it)&1) ? 16u : 0u);
            cp16(bdst[it] + so, bbase + (size_t)it*bstride + pc*64, 16u);
        }
        CP_COMMIT();
    }

    #pragma unroll 1
    for (int kc = 0; kc < NCH; kc++){
        if (kc == NCH-1) { CP_WAIT(0); } else { CP_WAIT(1); }
        __syncthreads();
        uint32_t so = (kc%3)*STAGE_B;
        #pragma unroll
        for (int kk = 0; kk < 4; kk++){
            uint32_t a[4][4];
            #pragma unroll
            for (int mf = 0; mf < 4; mf++){
                uint32_t sl = (uint32_t)(2*kk) + a_sl_hi;
                ldsm4(a[mf][0], a[mf][1], a[mf][2], a[mf][3], (albase[mf] ^ (sl<<4)) + so);
            }
            uint32_t b[8][2];
            #pragma unroll
            for (int j = 0; j < 4; j++){
                uint32_t sl = (uint32_t)(2*kk) + b_sl_hi;
                ldsm4(b[2*j][0], b[2*j][1], b[2*j+1][0], b[2*j+1][1], (blbase[j] ^ (sl<<4)) + so);
            }
            #pragma unroll
            for (int mf = 0; mf < 4; mf++)
                #pragma unroll
                for (int nf = 0; nf < 8; nf++)
                    mma_f16(c[mf][nf][0], c[mf][nf][1], c[mf][nf][2], c[mf][nf][3],
                            a[mf][0], a[mf][1], a[mf][2], a[mf][3],
                            b[nf][0], b[nf][1]);
            if (kk == 0 && kc + 2 < NCH){
                uint32_t po = ((kc+2)%3)*STAGE_B;
                #pragma unroll
                for (int it = 0; it < 8; it++){
                    cp16(adst[it] + po, abase + aoff[it] + (size_t)(kc+2)*128, ((amask>>it)&1) ? 16u : 0u);
                    cp16(bdst[it] + po, bbase + (size_t)it*bstride + (size_t)(kc+2)*64, 16u);
                }
                CP_COMMIT();
            }
        }
    }

    if (MODE == 0){
        __syncthreads();
        __half* ep = (__half*)smem;
        #pragma unroll
        for (int mf = 0; mf < 4; mf++){
            #pragma unroll
            for (int i2 = 0; i2 < 2; i2++){
                int mrow = wm*64 + mf*16 + i2*8 + g;
                __half* er = ep + mrow*EP_PITCH + wn*32;
                #pragma unroll
                for (int nf = 0; nf < 8; nf++){
                    float h = c[mf][nf][i2*2 + 0];
                    float v = c[mf][nf][i2*2 + 1];
                    er[nf*4 + t] = __float2half_rn(h * v / (1.f + __expf(-h)));
                }
            }
        }
        __syncthreads();
        int g8 = tid >> 3, sl = tid & 7;
        #pragma unroll
        for (int j = 0; j < 8; j++){
            int row = g8*8 + j;
            float4 v = *(const float4*)(ep + row*EP_PITCH + sl*8);
            *(float4*)(g_G + ((size_t)(e*CAP + mt*128 + row))*D_FF + nt*64 + sl*8) = v;
        }
        __threadfence();
        __syncthreads();
        if (tid == 0) atomicAdd(&g_done[e*32 + mt], 1);
    } else {
        #pragma unroll
        for (int mf = 0; mf < 4; mf++){
            #pragma unroll
            for (int i2 = 0; i2 < 2; i2++){
                int m = mt*128 + wm*64 + mf*16 + i2*8 + g;
                __half* yd = g_Y + ((size_t)(e*CAP + m))*D_MODEL + nt*128 + wn*64;
                #pragma unroll
                for (int nf = 0; nf < 8; nf++){
                    __half2 o = __floats2half2_rn(c[mf][nf][i2*2 + 0], c[mf][nf][i2*2 + 1]);
                    *(__half2*)(yd + nf*8 + 2*t) = o;
                }
            }
        }
    }
}

// ---------------- fused GEMM1+GEMM2 (launch 2) ----------------
__global__ void __launch_bounds__(128, 2) gemm_fused_kernel(){
    extern __shared__ char smem[];
    int bid = blockIdx.x;
    if (bid < G1_BLOCKS){
        int nt = bid & 63, mt = (bid >> 6) & 31, e = bid >> 11;
        int c0 = g_cnt_raw[e]; int cnt = c0 < CAP ? c0 : CAP;
        if (mt*128 >= cnt) return;
        gemm_body<0>(nt, mt, e, cnt, smem);
    } else {
        int b = bid - G1_BLOCKS;
        int nt = b & 7, mt = (b >> 3) & 31, e = b >> 8;
        int c0 = g_cnt_raw[e]; int cnt = c0 < CAP ? c0 : CAP;
        if (mt*128 >= cnt) return;
        if (threadIdx.x == 0){
            while (atomicAdd(&g_done[e*32 + mt], 0) < 64) __nanosleep(200);
        }
        __syncthreads();
        __threadfence();
        gemm_body<1>(nt, mt, e, cnt, smem);
    }
}

// ---------------- weighted top-k combine (launch 3), fp16 Y ----------------
__global__ void combine_kernel(const float* __restrict__ ew, float* __restrict__ out){
    int i = blockIdx.x * blockDim.x + threadIdx.x;
    if (i >= N_TOKENS*D_MODEL/4) return;
    int tok = i >> 8;
    int d4 = i & 255;
    float4 acc = make_float4(0.f,0.f,0.f,0.f);
    #pragma unroll
    for (int k = 0; k < TOPK; k++){
        int s = g_slotof[2*tok + k];
        if (s >= 0){
            float w = ew[2*tok + k];
            const __half2* yv = (const __half2*)(g_Y + (size_t)s*D_MODEL);
            float2 a0 = __half22float2(yv[2*d4]);
            float2 a1 = __half22float2(yv[2*d4 + 1]);
            acc.x += w*a0.x; acc.y += w*a0.y; acc.z += w*a1.x; acc.w += w*a1.y;
        }
    }
    ((float4*)out)[i] = acc;
}

extern "C" void kernel_launch(void* const* d_in, const int* in_sizes, int n_in,
                              void* d_out, int out_size) {
    const float* x   = (const float*)d_in[0];
    const int*   idx = (const int*)  d_in[1];
    const float* ew  = (const float*)d_in[2];
    const float* w1  = (const float*)d_in[3];
    const float* w2  = (const float*)d_in[4];
    const float* w3  = (const float*)d_in[5];
    float* out = (float*)d_out;

    cudaFuncSetAttribute(gemm_fused_kernel, cudaFuncAttributeMaxDynamicSharedMemorySize, SMEM_BYTES);

    init_kernel<<<1, 256>>>();                                        // 0
    prep_kernel<<<PREP_BLOCKS, 256>>>(idx, x, w1, w2, w3);            // 1 (route + x + transposes)
    gemm_fused_kernel<<<G1_BLOCKS + G2_BLOCKS, 128, SMEM_BYTES>>>();  // 2
    combine_kernel<<<(N_TOKENS*D_MODEL/4)/256, 256>>>(ew, out);       // 3
}